// round 1
// baseline (speedup 1.0000x reference)
#include <cuda_runtime.h>
#include <math.h>

// ---------------- scratch (no allocations allowed) ----------------
__device__ long long g_rowbase[2048];        // (b*4096+idx)*768 per (b,k)
__device__ float     g_score[2048];          // attention scores, init to v_b
__device__ float     g_z[128 * 768];         // pooled features

#define NEG_INF (-3.402823466e38f)

// ---------------- f32x2 packed-FMA helpers (sm_103a) ----------------
__device__ __forceinline__ unsigned long long pack2(float x, float y) {
    unsigned long long r;
    asm("mov.b64 %0, {%1, %2};" : "=l"(r) : "f"(x), "f"(y));
    return r;
}
__device__ __forceinline__ void unpack2(unsigned long long p, float& x, float& y) {
    asm("mov.b64 {%0, %1}, %2;" : "=f"(x), "=f"(y) : "l"(p));
}
__device__ __forceinline__ void fma2(unsigned long long& acc,
                                     unsigned long long a, unsigned long long b) {
    asm("fma.rn.f32x2 %0, %1, %2, %0;" : "+l"(acc) : "l"(a), "l"(b));
}

// ---------------- kernel 1: per-batch top-16 of r ----------------
// 128 blocks x 256 threads; each thread owns 16 strided elements in registers.
__global__ void topk_kernel(const float* __restrict__ r,
                            const float* __restrict__ vb) {
    const int b = blockIdx.x;
    const int t = threadIdx.x;
    float rv[16];
#pragma unroll
    for (int s = 0; s < 16; s++) rv[s] = r[b * 4096 + s * 256 + t];

    __shared__ float s_v[8];
    __shared__ int   s_p[8];
    __shared__ int   w_p;
    const float vbv = vb[0];

    for (int it = 0; it < 16; it++) {
        float bv = NEG_INF; int bs = 0;
#pragma unroll
        for (int s = 0; s < 16; s++)
            if (rv[s] > bv) { bv = rv[s]; bs = s; }
        int pay = (t << 4) | bs;
#pragma unroll
        for (int off = 16; off > 0; off >>= 1) {
            float ov = __shfl_down_sync(0xffffffffu, bv, off);
            int   op = __shfl_down_sync(0xffffffffu, pay, off);
            if (ov > bv) { bv = ov; pay = op; }
        }
        if ((t & 31) == 0) { s_v[t >> 5] = bv; s_p[t >> 5] = pay; }
        __syncthreads();
        if (t == 0) {
            float best = s_v[0]; int bp = s_p[0];
#pragma unroll
            for (int w = 1; w < 8; w++)
                if (s_v[w] > best) { best = s_v[w]; bp = s_p[w]; }
            w_p = bp;
            int wt = bp >> 4, ws = bp & 15;
            int idx = ws * 256 + wt;
            g_rowbase[b * 16 + it] = ((long long)b * 4096 + idx) * 768;
            g_score[b * 16 + it] = vbv;   // init score with v bias
        }
        __syncthreads();
        int bp = w_p;
        if (t == (bp >> 4)) rv[bp & 15] = NEG_INF;
    }
}

// ---------------- kernel 2: fused GEMM1 + tanh + v-dot -> score ----------------
// A = gathered x rows [2048,768], B = pool_W_w [768,768].
// 64x64 tile, BK=16, 128 threads, rm=8 x rn=4 per thread, f32x2 accumulators.
__global__ void gemm1_kernel(const float* __restrict__ x,
                             const float* __restrict__ W,
                             const float* __restrict__ Wb,
                             const float* __restrict__ v) {
    __shared__ float As[16][64];   // transposed: As[k][m]
    __shared__ float Bs[16][64];   // Bs[k][n]
    __shared__ long long rb[64];

    const int t = threadIdx.x;
    const int n0 = blockIdx.x * 64;
    const int m0 = blockIdx.y * 64;
    if (t < 64) rb[t] = g_rowbase[m0 + t];

    const int tx = t & 15;   // n: rn=4 -> covers 64
    const int ty = t >> 4;   // m: rm=8 -> covers 64

    unsigned long long acc[8][2] = {};
    __syncthreads();

    for (int k0 = 0; k0 < 768; k0 += 16) {
        for (int s = t; s < 256; s += 128) {
            int ml = s >> 2, kg = s & 3;
            const float4 a = *(const float4*)(x + rb[ml] + k0 + kg * 4);
            As[kg * 4 + 0][ml] = a.x;
            As[kg * 4 + 1][ml] = a.y;
            As[kg * 4 + 2][ml] = a.z;
            As[kg * 4 + 3][ml] = a.w;
        }
        for (int s = t; s < 256; s += 128) {
            int kr = s >> 4, ng = s & 15;
            *(float4*)&Bs[kr][ng * 4] =
                *(const float4*)(W + (size_t)(k0 + kr) * 768 + n0 + ng * 4);
        }
        __syncthreads();
#pragma unroll
        for (int k = 0; k < 16; k++) {
            const float4 aA = *(const float4*)&As[k][ty * 8];
            const float4 aB = *(const float4*)&As[k][ty * 8 + 4];
            const ulonglong2 bb = *(const ulonglong2*)&Bs[k][tx * 4];
            float av[8] = {aA.x, aA.y, aA.z, aA.w, aB.x, aB.y, aB.z, aB.w};
#pragma unroll
            for (int i = 0; i < 8; i++) {
                unsigned long long ap = pack2(av[i], av[i]);
                fma2(acc[i][0], ap, bb.x);
                fma2(acc[i][1], ap, bb.y);
            }
        }
        __syncthreads();
    }

    // epilogue: tanh(h + Wb) dot v -> partial score, reduce over tx group
    const int nb = n0 + tx * 4;
    const float wb0 = Wb[nb], wb1 = Wb[nb + 1], wb2 = Wb[nb + 2], wb3 = Wb[nb + 3];
    const float v0 = v[nb], v1 = v[nb + 1], v2 = v[nb + 2], v3 = v[nb + 3];
#pragma unroll
    for (int i = 0; i < 8; i++) {
        float c0, c1, c2, c3;
        unpack2(acc[i][0], c0, c1);
        unpack2(acc[i][1], c2, c3);
        float p = tanhf(c0 + wb0) * v0 + tanhf(c1 + wb1) * v1 +
                  tanhf(c2 + wb2) * v2 + tanhf(c3 + wb3) * v3;
#pragma unroll
        for (int off = 8; off > 0; off >>= 1)
            p += __shfl_xor_sync(0xffffffffu, p, off, 16);
        if (tx == 0) atomicAdd(&g_score[m0 + ty * 8 + i], p);
    }
}

// ---------------- kernel 3: softmax over K=16, z = sum alpha*x ----------------
__global__ void softz_kernel(const float* __restrict__ x) {
    const int b = blockIdx.x;
    const int t = threadIdx.x;  // 192 -> 768/4 float4 per thread
    float sc[16];
#pragma unroll
    for (int k = 0; k < 16; k++) sc[k] = g_score[b * 16 + k];
    float mx = sc[0];
#pragma unroll
    for (int k = 1; k < 16; k++) mx = fmaxf(mx, sc[k]);
    float sum = 0.f;
#pragma unroll
    for (int k = 0; k < 16; k++) { sc[k] = expf(sc[k] - mx); sum += sc[k]; }
    const float inv = 1.0f / sum;

    float4 z = make_float4(0.f, 0.f, 0.f, 0.f);
#pragma unroll
    for (int k = 0; k < 16; k++) {
        const float a = sc[k] * inv;
        const float4 xv = *(const float4*)(x + g_rowbase[b * 16 + k] + t * 4);
        z.x += a * xv.x; z.y += a * xv.y; z.z += a * xv.z; z.w += a * xv.w;
    }
    *(float4*)&g_z[b * 768 + t * 4] = z;
}

// ---------------- kernel 4: init output with fc bias ----------------
__global__ void initout_kernel(float* __restrict__ out,
                               const float* __restrict__ fcb) {
    const int b = blockIdx.x;
    for (int n = threadIdx.x; n < 1000; n += 256)
        out[b * 1000 + n] = fcb[n];
}

// ---------------- kernel 5: fc GEMM [128,768]x[768,1000], split-K, atomic ----------------
__global__ void fc_kernel(const float* __restrict__ Wfc, float* __restrict__ out) {
    __shared__ float As[16][64];
    __shared__ float Bs[16][64];
    const int t = threadIdx.x;
    const int n0 = blockIdx.x * 64;
    const int m0 = blockIdx.y * 64;
    const int kbase = blockIdx.z * 128;
    const int tx = t & 15, ty = t >> 4;

    unsigned long long acc[8][2] = {};

    for (int kt = 0; kt < 128; kt += 16) {
        const int k0 = kbase + kt;
        for (int s = t; s < 256; s += 128) {
            int ml = s >> 2, kg = s & 3;
            const float4 a = *(const float4*)(g_z + (m0 + ml) * 768 + k0 + kg * 4);
            As[kg * 4 + 0][ml] = a.x;
            As[kg * 4 + 1][ml] = a.y;
            As[kg * 4 + 2][ml] = a.z;
            As[kg * 4 + 3][ml] = a.w;
        }
        for (int e = t; e < 1024; e += 128) {
            int kr = e >> 6, nc = e & 63;
            int n = n0 + nc;
            Bs[kr][nc] = (n < 1000) ? Wfc[(size_t)(k0 + kr) * 1000 + n] : 0.f;
        }
        __syncthreads();
#pragma unroll
        for (int k = 0; k < 16; k++) {
            const float4 aA = *(const float4*)&As[k][ty * 8];
            const float4 aB = *(const float4*)&As[k][ty * 8 + 4];
            const ulonglong2 bb = *(const ulonglong2*)&Bs[k][tx * 4];
            float av[8] = {aA.x, aA.y, aA.z, aA.w, aB.x, aB.y, aB.z, aB.w};
#pragma unroll
            for (int i = 0; i < 8; i++) {
                unsigned long long ap = pack2(av[i], av[i]);
                fma2(acc[i][0], ap, bb.x);
                fma2(acc[i][1], ap, bb.y);
            }
        }
        __syncthreads();
    }

#pragma unroll
    for (int i = 0; i < 8; i++) {
        const int m = m0 + ty * 8 + i;
        float c0, c1, c2, c3;
        unpack2(acc[i][0], c0, c1);
        unpack2(acc[i][1], c2, c3);
        const int n = n0 + tx * 4;
        if (n + 0 < 1000) atomicAdd(&out[m * 1000 + n + 0], c0);
        if (n + 1 < 1000) atomicAdd(&out[m * 1000 + n + 1], c1);
        if (n + 2 < 1000) atomicAdd(&out[m * 1000 + n + 2], c2);
        if (n + 3 < 1000) atomicAdd(&out[m * 1000 + n + 3], c3);
    }
}

// ---------------- launch ----------------
extern "C" void kernel_launch(void* const* d_in, const int* in_sizes, int n_in,
                              void* d_out, int out_size) {
    const float* x    = (const float*)d_in[0];   // [128,4096,768]
    const float* r    = (const float*)d_in[1];   // [128,4096]
    const float* pWw  = (const float*)d_in[2];   // [768,768]
    const float* pWb  = (const float*)d_in[3];   // [768]
    const float* pVw  = (const float*)d_in[4];   // [768,1]
    const float* pVb  = (const float*)d_in[5];   // [1]
    const float* fcw  = (const float*)d_in[6];   // [768,1000]
    const float* fcb  = (const float*)d_in[7];   // [1000]
    float* out = (float*)d_out;                  // [128,1000]

    topk_kernel<<<128, 256>>>(r, pVb);
    gemm1_kernel<<<dim3(12, 32), 128>>>(x, pWw, pWb, pVw);
    softz_kernel<<<128, 192>>>(x);
    initout_kernel<<<128, 256>>>(out, fcb);
    fc_kernel<<<dim3(16, 2, 6), 128>>>(fcw, out);
}